// round 13
// baseline (speedup 1.0000x reference)
#include <cuda_runtime.h>
#include <cstdint>

#define CD 512
#define KD 65536
#define BM 128
#define BK 64
#define NPAIRS 10
#define NJOBS (NPAIRS * 1024)        // 1024 chunks of 64 k per pair
#define NCTA 148
#define NSLOT 3
#define WSTRIDE 36                   // words per smem row (frag LDS conflict-free)
#define TILE_W (BM * WSTRIDE)
#define STAGE_W (2 * TILE_W)
#define SMEM_BYTES (NSLOT * STAGE_W * 4)   // 110592 B -> 1 CTA/SM

// Deterministic partial-tile scratch + arrival counters (no device allocation)
__device__ float g_part[(size_t)NCTA * 2 * 16384];
__device__ int g_ctr[NPAIRS];

__device__ __forceinline__ uint32_t s2u(const void* p) {
    uint32_t a;
    asm("{ .reg .u64 t; cvta.to.shared.u64 t, %1; cvt.u32.u64 %0, t; }" : "=r"(a) : "l"(p));
    return a;
}
__device__ __forceinline__ uint32_t bf2(float x, float y) {
    uint32_t r;
    asm("cvt.rn.bf16x2.f32 %0, %1, %2;" : "=r"(r) : "f"(y), "f"(x));
    return r;
}
__device__ __forceinline__ void sts64(uint32_t a, uint32_t w0, uint32_t w1) {
    asm volatile("st.shared.v2.b32 [%0], {%1, %2};" :: "r"(a), "r"(w0), "r"(w1) : "memory");
}
__device__ __forceinline__ void bar_wait(int id) {
    asm volatile("bar.sync %0, 256;" :: "r"(id) : "memory");
}
__device__ __forceinline__ void bar_post(int id) {
    asm volatile("bar.arrive %0, 256;" :: "r"(id) : "memory");
}
__device__ __forceinline__ int job_lo(int s) { return (int)((long long)s * NJOBS / NCTA); }
__device__ __forceinline__ void pair_ij(int p, int& bi, int& bj) {
    bi = 0;
    while ((bi + 1) * (bi + 2) / 2 <= p) bi++;
    bj = p - bi * (bi + 1) / 2;
}

__global__ __launch_bounds__(256, 1) void gram_fused(const float* __restrict__ X,
                                                     float* __restrict__ out) {
    extern __shared__ uint32_t smw[];
    __shared__ int s_cl[NCTA];       // compacted contributor plane list
    __shared__ int s_cn;
    __shared__ int s_flag;

    const uint32_t sb = s2u(smw);
    const int tid  = threadIdx.x;
    const int lane = tid & 31;
    const int wid  = tid >> 5;

    const int jb = job_lo(blockIdx.x);
    const int je = job_lo(blockIdx.x + 1);

    // segment table (<= 2 segments per CTA); pure function of jb/je
    int segp[2] = {-1, -1};
    int nseg = 0;
    for (int j = jb; j < je; j = min(je, ((j >> 10) + 1) << 10))
        segp[nseg++] = j >> 10;

    if (wid >= 4) {
        // ================= producers (warps 4-7): fp32 LDG -> cvt -> STS =================
        const int pu    = tid - 128;
        const int ptile = pu >> 6;
        const int pv    = pu & 63;
        const int pg    = pv & 15;          // float4 granule: k = 4*pg..4*pg+3
        const int prb   = pv >> 4;          // row base (rows prb + 4*kidx)
        const uint32_t tile_w = (uint32_t)(ptile ? TILE_W : 0);

        int it = 0, j = jb;
        while (j < je) {
            const int p = j >> 10;
            int bi, bj; pair_ij(p, bi, bj);
            const bool skip = (bi == bj) && (ptile == 1);
            const float* gp = X + (size_t)((ptile ? bj : bi) * BM + prb) * KD + 4 * pg;
            const int jend = min(je, (p + 1) << 10);
            for (; j < jend; ++j, ++it) {
                const int s = it % NSLOT;
                if (it >= NSLOT) bar_wait(4 + s);
                if (!skip) {
                    const float* g = gp + (size_t)(j & 1023) * BK;
                    const uint32_t base = sb + (uint32_t)(s * STAGE_W + tile_w) * 4u;
                    #pragma unroll
                    for (int b = 0; b < 2; b++) {
                        float4 v[16];
                        #pragma unroll
                        for (int k = 0; k < 16; k++)
                            v[k] = *(const float4*)(g + (size_t)(4 * (16 * b + k)) * KD);
                        #pragma unroll
                        for (int k = 0; k < 16; k++) {
                            const int row = prb + 4 * (16 * b + k);
                            sts64(base + (uint32_t)(row * WSTRIDE + 2 * pg) * 4u,
                                  bf2(v[k].x, v[k].y), bf2(v[k].z, v[k].w));
                        }
                    }
                }
                bar_post(1 + s);
            }
        }
    } else {
        // ================= consumers (warps 0-3): bf16 m16n8k16 mma =================
        const int wr = wid >> 1, wc = wid & 1;
        const int g = lane >> 2, t = lane & 3;

        int it = 0, j = jb, seg = 0;
        while (j < je) {
            const int p = j >> 10;
            int bi, bj; pair_ij(p, bi, bj);
            const bool diag = (bi == bj);
            const int jend = min(je, (p + 1) << 10);

            float acc[4][8][4];
            #pragma unroll
            for (int mi = 0; mi < 4; mi++)
                #pragma unroll
                for (int ni = 0; ni < 8; ni++)
                    #pragma unroll
                    for (int e = 0; e < 4; e++) acc[mi][ni][e] = 0.f;

            for (; j < jend; ++j, ++it) {
                const int s = it % NSLOT;
                bar_wait(1 + s);
                const uint32_t* As = smw + s * STAGE_W;
                const uint32_t* Bs = diag ? As : (As + TILE_W);
                #pragma unroll
                for (int kk = 0; kk < 4; kk++) {
                    const int kw = kk * 8 + t;
                    uint32_t ar[4][4];
                    #pragma unroll
                    for (int mi = 0; mi < 4; mi++) {
                        const int r = 64 * wr + 16 * mi + g;
                        ar[mi][0] = As[r * WSTRIDE + kw];
                        ar[mi][1] = As[(r + 8) * WSTRIDE + kw];
                        ar[mi][2] = As[r * WSTRIDE + kw + 4];
                        ar[mi][3] = As[(r + 8) * WSTRIDE + kw + 4];
                    }
                    uint32_t br[8][2];
                    #pragma unroll
                    for (int ni = 0; ni < 8; ni++) {
                        const int n = 64 * wc + 8 * ni + g;
                        br[ni][0] = Bs[n * WSTRIDE + kw];
                        br[ni][1] = Bs[n * WSTRIDE + kw + 4];
                    }
                    #pragma unroll
                    for (int mi = 0; mi < 4; mi++)
                        #pragma unroll
                        for (int ni = 0; ni < 8; ni++) {
                            asm volatile(
                                "mma.sync.aligned.m16n8k16.row.col.f32.bf16.bf16.f32 "
                                "{%0,%1,%2,%3}, {%4,%5,%6,%7}, {%8,%9}, {%0,%1,%2,%3};"
                                : "+f"(acc[mi][ni][0]), "+f"(acc[mi][ni][1]),
                                  "+f"(acc[mi][ni][2]), "+f"(acc[mi][ni][3])
                                : "r"(ar[mi][0]), "r"(ar[mi][1]), "r"(ar[mi][2]), "r"(ar[mi][3]),
                                  "r"(br[ni][0]), "r"(br[ni][1]));
                        }
                }
                bar_post(4 + s);
            }

            // epilogue: partial 128x128 tile -> plane (blockIdx.x*2 + seg)
            float* pl = g_part + ((size_t)blockIdx.x * 2 + seg) * 16384;
            #pragma unroll
            for (int mi = 0; mi < 4; mi++) {
                const int r = 64 * wr + 16 * mi + g;
                #pragma unroll
                for (int ni = 0; ni < 8; ni++) {
                    const int c = 64 * wc + 8 * ni + 2 * t;
                    *(float2*)(pl + r * 128 + c)       = make_float2(acc[mi][ni][0], acc[mi][ni][1]);
                    *(float2*)(pl + (r + 8) * 128 + c) = make_float2(acc[mi][ni][2], acc[mi][ni][3]);
                }
            }
            seg++;
        }
        __threadfence();     // make partials visible before arrival
    }

    __syncthreads();

    // ================= fused deterministic reduction tail =================
    for (int si = 0; si < nseg; si++) {
        const int p = segp[si];
        if (tid == 0) {
            int np = 0, n = 0;
            for (int s = 0; s < NCTA; s++) {
                const int sj0 = job_lo(s), sj1 = job_lo(s + 1);
                if (sj0 < ((p + 1) << 10) && sj1 > (p << 10)) {
                    np++;
                    s_cl[n++] = s * 2 + (((sj0 >> 10) == p) ? 0 : 1);
                }
            }
            s_cn = n;
            const int old = atomicAdd(&g_ctr[p], 1);
            s_flag = ((old + 1) % np == 0);
        }
        __syncthreads();
        if (s_flag) {
            __threadfence();                     // acquire contributors' writes
            int bi, bj; pair_ij(p, bi, bj);
            const int cn = s_cn;
            for (int q = 0; q < 64; q++) {
                const int e = tid + 256 * q;     // 0..16383
                float v = 0.f;
                for (int k = 0; k < cn; k++)     // fixed ascending order: deterministic
                    v += g_part[(size_t)s_cl[k] * 16384 + e];
                const int r = e >> 7, c = e & 127;
                out[(size_t)(bi * 128 + r) * CD + (bj * 128 + c)] = v;
                out[(size_t)(bj * 128 + c) * CD + (bi * 128 + r)] = v;
            }
        }
        __syncthreads();
    }
}

extern "C" void kernel_launch(void* const* d_in, const int* in_sizes, int n_in,
                              void* d_out, int out_size) {
    const float* x = (const float*)d_in[0];   // [1,512,256,256] = [512, 65536]
    float* out = (float*)d_out;               // [1,1,512,512]

    cudaFuncSetAttribute(gram_fused, cudaFuncAttributeMaxDynamicSharedMemorySize, SMEM_BYTES);
    gram_fused<<<NCTA, 256, SMEM_BYTES>>>(x, out);
}

// round 14
// speedup vs baseline: 1.9943x; 1.9943x over previous
#include <cuda_runtime.h>
#include <cstdint>

#define CD 512
#define KD 65536
#define BM 128
#define BK 64
#define NPAIRS 10
#define SPLITS 14
#define NCHUNK (KD / BK)             // 1024
#define NSLOT 4
#define WSTRIDE 36                   // words per smem row (frag LDS conflict-free)
#define TILE_W (BM * WSTRIDE)
#define STAGE_W (2 * TILE_W)
#define SMEM_BYTES (NSLOT * STAGE_W * 4)   // 147456 B -> 1 CTA/SM

// Deterministic partial planes + per-pair arrival counters (no device allocation)
__device__ float g_part[(size_t)NPAIRS * SPLITS * 16384];
__device__ int g_ctr[NPAIRS];

__device__ __forceinline__ uint32_t s2u(const void* p) {
    uint32_t a;
    asm("{ .reg .u64 t; cvta.to.shared.u64 t, %1; cvt.u32.u64 %0, t; }" : "=r"(a) : "l"(p));
    return a;
}
__device__ __forceinline__ uint32_t bf2(float x, float y) {
    uint32_t r;
    asm("cvt.rn.bf16x2.f32 %0, %1, %2;" : "=r"(r) : "f"(y), "f"(x));
    return r;
}
__device__ __forceinline__ void sts64(uint32_t a, uint32_t w0, uint32_t w1) {
    asm volatile("st.shared.v2.b32 [%0], {%1, %2};" :: "r"(a), "r"(w0), "r"(w1) : "memory");
}
__device__ __forceinline__ void bar_wait(int id) {
    asm volatile("bar.sync %0, 256;" :: "r"(id) : "memory");
}
__device__ __forceinline__ void bar_post(int id) {
    asm volatile("bar.arrive %0, 256;" :: "r"(id) : "memory");
}

__global__ __launch_bounds__(256, 1) void gram_fused(const float* __restrict__ X,
                                                     float* __restrict__ out) {
    extern __shared__ uint32_t smw[];
    __shared__ int s_flag;

    const uint32_t sb = s2u(smw);
    const int tid  = threadIdx.x;
    const int lane = tid & 31;
    const int wid  = tid >> 5;

    const int pair  = blockIdx.x % NPAIRS;
    const int split = blockIdx.x / NPAIRS;

    int bi = 0;
    while ((bi + 1) * (bi + 2) / 2 <= pair) bi++;
    const int bj = pair - bi * (bi + 1) / 2;
    const bool diag = (bi == bj);

    const int c0 = (split * NCHUNK) / SPLITS;
    const int c1 = ((split + 1) * NCHUNK) / SPLITS;
    const int niters = c1 - c0;

    if (wid >= 4) {
        // ================= producers (warps 4-7): fp32 LDG -> cvt -> STS =================
        const int pu    = tid - 128;
        const int ptile = pu >> 6;          // 0 = A tile, 1 = B tile
        const int pv    = pu & 63;
        const int pg    = pv & 15;          // float4 granule: k = 4*pg..4*pg+3
        const int prb   = pv >> 4;          // row base (rows prb + 4*kidx)
        const bool skip = diag && (ptile == 1);
        const uint32_t tile_w = (uint32_t)(ptile ? TILE_W : 0);
        const float* gp = X + (size_t)((ptile ? bj : bi) * BM + prb) * KD + 4 * pg;

        for (int i = 0; i < niters; i++) {
            const int s = i % NSLOT;
            if (i >= NSLOT) bar_wait(8 + s);          // wait slot empty
            if (!skip) {
                const float* g = gp + (size_t)(c0 + i) * BK;
                const uint32_t base = sb + (uint32_t)(s * STAGE_W + tile_w) * 4u;
                #pragma unroll
                for (int b = 0; b < 2; b++) {
                    float4 v[16];
                    #pragma unroll
                    for (int k = 0; k < 16; k++)
                        v[k] = *(const float4*)(g + (size_t)(4 * (16 * b + k)) * KD);
                    #pragma unroll
                    for (int k = 0; k < 16; k++) {
                        const int row = prb + 4 * (16 * b + k);
                        sts64(base + (uint32_t)(row * WSTRIDE + 2 * pg) * 4u,
                              bf2(v[k].x, v[k].y), bf2(v[k].z, v[k].w));
                    }
                }
            }
            bar_post(1 + s);                          // signal slot full
        }
    } else {
        // ================= consumers (warps 0-3): bf16 m16n8k16 mma =================
        const int wr = wid >> 1;            // 0..1 -> rows 64*wr
        const int wc = wid & 1;             // 0..1 -> cols 64*wc
        const int g  = lane >> 2;           // 0..7
        const int t  = lane & 3;            // 0..3

        float acc[4][8][4];
        #pragma unroll
        for (int mi = 0; mi < 4; mi++)
            #pragma unroll
            for (int ni = 0; ni < 8; ni++)
                #pragma unroll
                for (int e = 0; e < 4; e++) acc[mi][ni][e] = 0.f;

        for (int i = 0; i < niters; i++) {
            const int s = i % NSLOT;
            bar_wait(1 + s);                          // wait slot full

            const uint32_t* As = smw + s * STAGE_W;
            const uint32_t* Bs = diag ? As : (As + TILE_W);

            #pragma unroll
            for (int kk = 0; kk < 4; kk++) {
                const int kw = kk * 8 + t;
                uint32_t ar[4][4];
                #pragma unroll
                for (int mi = 0; mi < 4; mi++) {
                    const int r = 64 * wr + 16 * mi + g;
                    ar[mi][0] = As[r * WSTRIDE + kw];
                    ar[mi][1] = As[(r + 8) * WSTRIDE + kw];
                    ar[mi][2] = As[r * WSTRIDE + kw + 4];
                    ar[mi][3] = As[(r + 8) * WSTRIDE + kw + 4];
                }
                uint32_t br[8][2];
                #pragma unroll
                for (int ni = 0; ni < 8; ni++) {
                    const int n = 64 * wc + 8 * ni + g;
                    br[ni][0] = Bs[n * WSTRIDE + kw];
                    br[ni][1] = Bs[n * WSTRIDE + kw + 4];
                }
                #pragma unroll
                for (int mi = 0; mi < 4; mi++)
                    #pragma unroll
                    for (int ni = 0; ni < 8; ni++) {
                        asm volatile(
                            "mma.sync.aligned.m16n8k16.row.col.f32.bf16.bf16.f32 "
                            "{%0,%1,%2,%3}, {%4,%5,%6,%7}, {%8,%9}, {%0,%1,%2,%3};"
                            : "+f"(acc[mi][ni][0]), "+f"(acc[mi][ni][1]),
                              "+f"(acc[mi][ni][2]), "+f"(acc[mi][ni][3])
                            : "r"(ar[mi][0]), "r"(ar[mi][1]), "r"(ar[mi][2]), "r"(ar[mi][3]),
                              "r"(br[ni][0]), "r"(br[ni][1]));
                    }
            }
            bar_post(8 + s);                          // signal slot empty
        }

        // epilogue: partial 128x128 tile -> contiguous plane blockIdx.x
        float* pl = g_part + (size_t)blockIdx.x * 16384;
        #pragma unroll
        for (int mi = 0; mi < 4; mi++) {
            const int r = 64 * wr + 16 * mi + g;
            #pragma unroll
            for (int ni = 0; ni < 8; ni++) {
                const int c = 64 * wc + 8 * ni + 2 * t;
                *(float2*)(pl + r * 128 + c)       = make_float2(acc[mi][ni][0], acc[mi][ni][1]);
                *(float2*)(pl + (r + 8) * 128 + c) = make_float2(acc[mi][ni][2], acc[mi][ni][3]);
            }
        }
        __threadfence();     // release partial plane before arrival
    }

    __syncthreads();

    // ================= fused deterministic reduction tail =================
    if (tid == 0) {
        const int old = atomicAdd(&g_ctr[pair], 1);
        s_flag = ((old + 1) % SPLITS == 0);          // modulo: replay-safe, no reset
    }
    __syncthreads();

    if (s_flag) {
        __threadfence();                              // acquire contributors' planes
        #pragma unroll 1
        for (int q = 0; q < 64; q++) {
            const int e = tid + 256 * q;              // 0..16383
            float v = 0.f;
            #pragma unroll
            for (int k = 0; k < SPLITS; k++)          // fixed ascending order: deterministic
                v += g_part[(size_t)(pair + NPAIRS * k) * 16384 + e];
            const int r = e >> 7, c = e & 127;
            out[(size_t)(bi * BM + r) * CD + (bj * BM + c)] = v;
            out[(size_t)(bj * BM + c) * CD + (bi * BM + r)] = v;
        }
    }
}

extern "C" void kernel_launch(void* const* d_in, const int* in_sizes, int n_in,
                              void* d_out, int out_size) {
    const float* x = (const float*)d_in[0];   // [1,512,256,256] = [512, 65536]
    float* out = (float*)d_out;               // [1,1,512,512]

    cudaFuncSetAttribute(gram_fused, cudaFuncAttributeMaxDynamicSharedMemorySize, SMEM_BYTES);
    gram_fused<<<NPAIRS * SPLITS, 256, SMEM_BYTES>>>(x, out);
}

// round 15
// speedup vs baseline: 2.6787x; 1.3432x over previous
#include <cuda_runtime.h>
#include <cstdint>

#define CD 512
#define KD 65536
#define BM 128
#define BK 64
#define NPAIRS 10
#define SPLITS 14
#define NCHUNK (KD / BK)             // 1024
#define NSLOT 3
#define WSTRIDE 36                   // words per smem row (frag LDS conflict-free)
#define TILE_W (BM * WSTRIDE)
#define STAGE_W (2 * TILE_W)
#define SMEM_BYTES (NSLOT * STAGE_W * 4)   // 110592 B -> 1 CTA/SM

// Deterministic split-K partial planes (no device allocation allowed)
__device__ float g_part[(size_t)NPAIRS * SPLITS * 16384];

__device__ __forceinline__ uint32_t s2u(const void* p) {
    uint32_t a;
    asm("{ .reg .u64 t; cvta.to.shared.u64 t, %1; cvt.u32.u64 %0, t; }" : "=r"(a) : "l"(p));
    return a;
}
__device__ __forceinline__ uint32_t bf2(float x, float y) {
    uint32_t r;
    asm("cvt.rn.bf16x2.f32 %0, %1, %2;" : "=r"(r) : "f"(y), "f"(x));
    return r;
}
__device__ __forceinline__ void sts64(uint32_t a, uint32_t w0, uint32_t w1) {
    asm volatile("st.shared.v2.b32 [%0], {%1, %2};" :: "r"(a), "r"(w0), "r"(w1) : "memory");
}
__device__ __forceinline__ void bar_wait(int id) {
    asm volatile("bar.sync %0, 256;" :: "r"(id) : "memory");
}
__device__ __forceinline__ void bar_post(int id) {
    asm volatile("bar.arrive %0, 256;" :: "r"(id) : "memory");
}

__global__ __launch_bounds__(256, 1) void gram_fused(const float* __restrict__ X) {
    extern __shared__ uint32_t smw[];
    const uint32_t sb = s2u(smw);

    const int pair  = blockIdx.x % NPAIRS;
    const int split = blockIdx.x / NPAIRS;

    int bi = 0;
    while ((bi + 1) * (bi + 2) / 2 <= pair) bi++;
    const int bj = pair - bi * (bi + 1) / 2;
    const bool diag = (bi == bj);

    const int c0 = (split * NCHUNK) / SPLITS;
    const int c1 = ((split + 1) * NCHUNK) / SPLITS;
    const int niters = c1 - c0;

    const int tid  = threadIdx.x;
    const int lane = tid & 31;
    const int wid  = tid >> 5;

    if (wid >= 4) {
        // ================= producers (warps 4-7): fp32 LDG -> cvt -> STS =================
        const int pu    = tid - 128;        // 0..127
        const int ptile = pu >> 6;          // 0 = A tile, 1 = B tile
        const int pv    = pu & 63;
        const int pg    = pv & 15;          // float4 granule: k = 4*pg .. 4*pg+3
        const int prb   = pv >> 4;          // row base 0..3 (rows prb + 4*kidx)
        const bool skip = diag && (ptile == 1);
        const uint32_t tile_w = (uint32_t)(ptile ? TILE_W : 0);
        const float* gp = X + (size_t)((ptile ? bj : bi) * BM + prb) * KD + 4 * pg;

        for (int i = 0; i < niters; i++) {
            const int s = i % NSLOT;
            if (i >= NSLOT) bar_wait(4 + s);          // wait slot empty
            if (!skip) {
                const float* g = gp + (size_t)(c0 + i) * BK;
                const uint32_t base = sb + (uint32_t)(s * STAGE_W + tile_w) * 4u;
                #pragma unroll
                for (int b = 0; b < 2; b++) {
                    float4 v[16];
                    #pragma unroll
                    for (int k = 0; k < 16; k++)
                        v[k] = *(const float4*)(g + (size_t)(4 * (16 * b + k)) * KD);
                    #pragma unroll
                    for (int k = 0; k < 16; k++) {
                        const int row = prb + 4 * (16 * b + k);
                        sts64(base + (uint32_t)(row * WSTRIDE + 2 * pg) * 4u,
                              bf2(v[k].x, v[k].y), bf2(v[k].z, v[k].w));
                    }
                }
            }
            bar_post(1 + s);                          // signal slot full
        }
        return;
    }

    // ================= consumers (warps 0-3): bf16 m16n8k16 mma =================
    const int wr = wid >> 1;            // 0..1 -> rows 64*wr
    const int wc = wid & 1;             // 0..1 -> cols 64*wc
    const int g  = lane >> 2;           // 0..7
    const int t  = lane & 3;            // 0..3

    float acc[4][8][4];
    #pragma unroll
    for (int mi = 0; mi < 4; mi++)
        #pragma unroll
        for (int ni = 0; ni < 8; ni++)
            #pragma unroll
            for (int e = 0; e < 4; e++) acc[mi][ni][e] = 0.f;

    for (int i = 0; i < niters; i++) {
        const int s = i % NSLOT;
        bar_wait(1 + s);                              // wait slot full

        const uint32_t* As = smw + s * STAGE_W;
        const uint32_t* Bs = diag ? As : (As + TILE_W);

        #pragma unroll
        for (int kk = 0; kk < 4; kk++) {
            const int kw = kk * 8 + t;
            uint32_t ar[4][4];
            #pragma unroll
            for (int mi = 0; mi < 4; mi++) {
                const int r = 64 * wr + 16 * mi + g;
                ar[mi][0] = As[r * WSTRIDE + kw];
                ar[mi][1] = As[(r + 8) * WSTRIDE + kw];
                ar[mi][2] = As[r * WSTRIDE + kw + 4];
                ar[mi][3] = As[(r + 8) * WSTRIDE + kw + 4];
            }
            uint32_t br[8][2];
            #pragma unroll
            for (int ni = 0; ni < 8; ni++) {
                const int n = 64 * wc + 8 * ni + g;
                br[ni][0] = Bs[n * WSTRIDE + kw];
                br[ni][1] = Bs[n * WSTRIDE + kw + 4];
            }
            #pragma unroll
            for (int mi = 0; mi < 4; mi++)
                #pragma unroll
                for (int ni = 0; ni < 8; ni++) {
                    asm volatile(
                        "mma.sync.aligned.m16n8k16.row.col.f32.bf16.bf16.f32 "
                        "{%0,%1,%2,%3}, {%4,%5,%6,%7}, {%8,%9}, {%0,%1,%2,%3};"
                        : "+f"(acc[mi][ni][0]), "+f"(acc[mi][ni][1]),
                          "+f"(acc[mi][ni][2]), "+f"(acc[mi][ni][3])
                        : "r"(ar[mi][0]), "r"(ar[mi][1]), "r"(ar[mi][2]), "r"(ar[mi][3]),
                          "r"(br[ni][0]), "r"(br[ni][1]));
                }
        }
        bar_post(4 + s);                              // signal slot empty
    }

    // epilogue: partial 128x128 tile -> contiguous plane (pair*SPLITS + split)
    float* pl = g_part + (size_t)(pair * SPLITS + split) * 16384;
    #pragma unroll
    for (int mi = 0; mi < 4; mi++) {
        const int r = 64 * wr + 16 * mi + g;
        #pragma unroll
        for (int ni = 0; ni < 8; ni++) {
            const int c = 64 * wc + 8 * ni + 2 * t;
            *(float2*)(pl + r * 128 + c)       = make_float2(acc[mi][ni][0], acc[mi][ni][1]);
            *(float2*)(pl + (r + 8) * 128 + c) = make_float2(acc[mi][ni][2], acc[mi][ni][3]);
        }
    }
}

// Sum 14 contiguous planes per pair; one float4 per thread; mirror to upper triangle.
__global__ void gram_reduce(float* __restrict__ out) {
    const int pair = blockIdx.x >> 4;                 // 16 blocks per pair
    const int e4   = ((blockIdx.x & 15) << 8) + threadIdx.x;   // 0..4095 float4 index

    int bi = 0;
    while ((bi + 1) * (bi + 2) / 2 <= pair) bi++;
    const int bj = pair - bi * (bi + 1) / 2;

    const float4* base = (const float4*)(g_part + (size_t)pair * SPLITS * 16384) + e4;
    float4 s = make_float4(0.f, 0.f, 0.f, 0.f);
    #pragma unroll
    for (int k = 0; k < SPLITS; k++) {
        const float4 v = base[k * 4096];
        s.x += v.x; s.y += v.y; s.z += v.z; s.w += v.w;
    }

    const int r = e4 >> 5;                            // 0..127
    const int c = (e4 & 31) << 2;                     // 0..124
    const int gi = bi * BM + r, gj = bj * BM + c;
    *(float4*)(out + (size_t)gi * CD + gj) = s;
    if (bi != bj) {                                   // mirror (diag tiles self-symmetric)
        out[(size_t)(gj + 0) * CD + gi] = s.x;
        out[(size_t)(gj + 1) * CD + gi] = s.y;
        out[(size_t)(gj + 2) * CD + gi] = s.z;
        out[(size_t)(gj + 3) * CD + gi] = s.w;
    } else {
        // diagonal tile: also fill its upper half (r<c region comes from mirror of r>c)
        out[(size_t)(gj + 0) * CD + gi] = s.x;
        out[(size_t)(gj + 1) * CD + gi] = s.y;
        out[(size_t)(gj + 2) * CD + gi] = s.z;
        out[(size_t)(gj + 3) * CD + gi] = s.w;
    }
}

extern "C" void kernel_launch(void* const* d_in, const int* in_sizes, int n_in,
                              void* d_out, int out_size) {
    const float* x = (const float*)d_in[0];   // [1,512,256,256] = [512, 65536]
    float* out = (float*)d_out;               // [1,1,512,512]

    cudaFuncSetAttribute(gram_fused, cudaFuncAttributeMaxDynamicSharedMemorySize, SMEM_BYTES);
    gram_fused<<<NPAIRS * SPLITS, 256, SMEM_BYTES>>>(x);
    gram_reduce<<<NPAIRS * 16, 256>>>(out);
}